// round 12
// baseline (speedup 1.0000x reference)
#include <cuda_runtime.h>
#include <cuda_bf16.h>
#include <cstdint>

#define NPTS 4096
#define BATCH 16
#define MCTR 1024
#define KNBR 64
#define OUTD 128
#define R2C  0.04f
#define CANDC 512

#define FPS_BLOCKS 16
#define FEAT_ROWS 64
#define FEAT_BLOCKS ((BATCH * NPTS) / FEAT_ROWS)     // 1024 (64 per batch)
#define PREP_ID   (FPS_BLOCKS + FEAT_BLOCKS)         // 1040
#define CENTER0   (PREP_ID + 1)                      // 1041
#define NCBLK     (BATCH * MCTR / 2)                 // 8192
#define GRID_ALL  (CENTER0 + NCBLK)                  // 9233

#define AST 36   // padded u32 stride for bf16-pair tiles

typedef unsigned long long ull;
typedef unsigned int u32;
typedef unsigned short u16;

// ---------------- device scratch ----------------
__device__ int   g_idx[BATCH * MCTR];
__device__ float g_feat[(size_t)BATCH * NPTS * 64];   // x @ W1[0:64,:]
__device__ u32   g_W2h[64 * 32],  g_W2l[64 * 32];     // W2^T bf16-pairs [n][k/2]
__device__ u32   g_W3h[128 * 32], g_W3l[128 * 32];    // W3^T bf16-pairs
__device__ int   g_sync[48];   // [0..15] fps m-progress, [16..31] feat done, [32] prep

// ---------------- acquire/release helpers ----------------
__device__ __forceinline__ int ld_acq(const int* p) {
    int v; asm volatile("ld.acquire.gpu.global.s32 %0, [%1];" : "=r"(v) : "l"(p)); return v;
}
__device__ __forceinline__ void st_rel(int* p, int v) {
    asm volatile("st.release.gpu.global.s32 [%0], %1;" :: "l"(p), "r"(v) : "memory");
}

// ---------------- f32x2 helpers ----------------
__device__ __forceinline__ ull fma2(ull a, ull b, ull c) {
    ull d; asm("fma.rn.f32x2 %0, %1, %2, %3;" : "=l"(d) : "l"(a), "l"(b), "l"(c));
    return d;
}
__device__ __forceinline__ ull pack2(float lo, float hi) {
    ull d; asm("mov.b64 %0, {%1, %2};" : "=l"(d) : "f"(lo), "f"(hi)); return d;
}
__device__ __forceinline__ float2 unpack2(ull v) {
    float2 r; asm("mov.b64 {%0, %1}, %2;" : "=f"(r.x), "=f"(r.y) : "l"(v)); return r;
}

// ---------------- mma.sync + ldmatrix ----------------
__device__ __forceinline__ void mma16816(float* c, u32 a0, u32 a1, u32 a2, u32 a3,
                                         u32 b0, u32 b1) {
    asm volatile(
        "mma.sync.aligned.m16n8k16.row.col.f32.bf16.bf16.f32 "
        "{%0,%1,%2,%3}, {%4,%5,%6,%7}, {%8,%9}, {%0,%1,%2,%3};"
        : "+f"(c[0]), "+f"(c[1]), "+f"(c[2]), "+f"(c[3])
        : "r"(a0), "r"(a1), "r"(a2), "r"(a3), "r"(b0), "r"(b1));
}
__device__ __forceinline__ void ldsm4(u32& r0, u32& r1, u32& r2, u32& r3, u32 a) {
    asm volatile("ldmatrix.sync.aligned.m8n8.x4.shared.b16 {%0,%1,%2,%3}, [%4];"
                 : "=r"(r0), "=r"(r1), "=r"(r2), "=r"(r3) : "r"(a));
}
__device__ __forceinline__ void ldsm2(u32& r0, u32& r1, u32 a) {
    asm volatile("ldmatrix.sync.aligned.m8n8.x2.shared.b16 {%0,%1}, [%2];"
                 : "=r"(r0), "=r"(r1) : "r"(a));
}

// ---------------- truncation-split packing (cheap) ----------------
// hi = top-16-bits of fp32 (exact, truncated); lo = v - hi (rounded to bf16).
// Dropped lo*lo term + lo rounding => ~2e-5 relative error, far under 1e-3.
__device__ __forceinline__ u32 pack_hi_trunc(float v0, float v1) {
    return __byte_perm(__float_as_uint(v0), __float_as_uint(v1), 0x7632);
}
__device__ __forceinline__ u32 pack_lo_trunc(float v0, float v1) {
    float l0 = v0 - __uint_as_float(__float_as_uint(v0) & 0xFFFF0000u);
    float l1 = v1 - __uint_as_float(__float_as_uint(v1) & 0xFFFF0000u);
    u32 r; asm("cvt.rn.bf16x2.f32 %0, %1, %2;" : "=r"(r) : "f"(l1), "f"(l0));
    return r;   // {lo half = l0, hi half = l1}
}

// ---------------- shared-memory layouts ----------------
struct CKS {
    ull   keys[2 * CANDC];
    u32   Ah[128 * AST];
    u32   Al[128 * AST];
    u32   W2h[64 * AST];
    u32   W2l[64 * AST];
    u32   W3h[128 * AST];
    u32   W3l[128 * AST];
    float pool[8][132];
    float b1s[64], b2s[64], b3s[128];
    float w1b[3 * 64];
    float rel[128 * 3];
    int   nbr[128];
    float ctr[6];
    int   cnt[2], nvv[2];
};

struct alignas(16) FSmem {
    union {
        struct {
            float px[NPTS], py[NPTS], pz[NPTS];
            ull   part[2][8];
        } fps;
        struct {
            float xx[FEAT_ROWS][65];
            float w[64][64];
        } feat;
        CKS center;
    } u;
};

// =========================================================================
__global__ __launch_bounds__(256, 2) void fused_kernel(
    const float* __restrict__ pos, float* __restrict__ pos_s_out,
    const float* __restrict__ x,   const float* __restrict__ W1,
    const float* __restrict__ W2,  const float* __restrict__ W3,
    const float* __restrict__ b1,  const float* __restrict__ b2,
    const float* __restrict__ b3,  float* __restrict__ out)
{
    extern __shared__ unsigned char smraw[];
    FSmem& sm = *reinterpret_cast<FSmem*>(smraw);
    int tid = threadIdx.x;

    if (blockIdx.x < FPS_BLOCKS) {
        // ========================= FPS (producer) =========================
        auto& S = sm.u.fps;
        int b = blockIdx.x;
        const float* pb = pos + (size_t)b * NPTS * 3;

        float px[16], py[16], pz[16], dst[16];
#pragma unroll
        for (int u = 0; u < 16; u++) {
            int i = tid + u * 256;
            float X = pb[i * 3 + 0], Y = pb[i * 3 + 1], Z = pb[i * 3 + 2];
            S.px[i] = X; S.py[i] = Y; S.pz[i] = Z;
            px[u] = X; py[u] = Y; pz[u] = Z;
            dst[u] = 1e10f;
        }
        __syncthreads();

        int   last = 0;
        float lx = S.px[0], ly = S.py[0], lz = S.pz[0];

        for (int m = 0; m < MCTR; m++) {
            if (tid == 0) {
                g_idx[b * MCTR + m] = last;
                float* po = pos_s_out + ((size_t)(b * MCTR + m)) * 3;
                po[0] = lx; po[1] = ly; po[2] = lz;
                st_rel(&g_sync[b], m + 1);
            }
            float bv = -1.0f; int bi = 0;
#pragma unroll
            for (int u = 0; u < 16; u++) {
                float dx = px[u] - lx, dy = py[u] - ly, dz = pz[u] - lz;
                float d  = fmaf(dx, dx, fmaf(dy, dy, dz * dz));
                float nd = fminf(dst[u], d);
                dst[u] = nd;
                int gi = tid + u * 256;
                if (nd > bv) { bv = nd; bi = gi; }
            }
            unsigned bvb  = __float_as_uint(bv);
            unsigned wmax = __reduce_max_sync(0xffffffffu, bvb);
            unsigned cand = (bvb == wmax) ? (unsigned)bi : 0xffffffffu;
            unsigned wbi  = __reduce_min_sync(0xffffffffu, cand);
            ull key = ((ull)wmax << 32) | (unsigned)(~wbi);
            if ((tid & 31) == 0) S.part[m & 1][tid >> 5] = key;
            __syncthreads();
            ull best = S.part[m & 1][0];
#pragma unroll
            for (int w = 1; w < 8; w++) {
                ull k2 = S.part[m & 1][w];
                if (k2 > best) best = k2;
            }
            last = (int)(~(unsigned)best);
            lx = S.px[last]; ly = S.py[last]; lz = S.pz[last];
        }
    } else if (blockIdx.x < PREP_ID) {
        // ========================= feat (producer) ========================
        auto& S = sm.u.feat;
        int fblk = blockIdx.x - FPS_BLOCKS;
        size_t rbase = (size_t)fblk * FEAT_ROWS;

        for (int i = tid; i < 64 * 64; i += 256) S.w[i >> 6][i & 63] = W1[i];
        for (int i = tid; i < FEAT_ROWS * 64; i += 256)
            S.xx[i >> 6][i & 63] = x[rbase * 64 + i];
        __syncthreads();

        int r = tid >> 2, q = tid & 3;
        ull acc[8];
#pragma unroll
        for (int c = 0; c < 8; c++) acc[c] = 0ull;
        for (int k = 0; k < 64; k++) {
            float xv = S.xx[r][k];
            ull xb = pack2(xv, xv);
            const ulonglong2* wp = reinterpret_cast<const ulonglong2*>(&S.w[k][q * 16]);
            ulonglong2 w0 = wp[0], w1 = wp[1], w2 = wp[2], w3 = wp[3];
            acc[0] = fma2(xb, w0.x, acc[0]); acc[1] = fma2(xb, w0.y, acc[1]);
            acc[2] = fma2(xb, w1.x, acc[2]); acc[3] = fma2(xb, w1.y, acc[3]);
            acc[4] = fma2(xb, w2.x, acc[4]); acc[5] = fma2(xb, w2.y, acc[5]);
            acc[6] = fma2(xb, w3.x, acc[6]); acc[7] = fma2(xb, w3.y, acc[7]);
        }
        float* go = g_feat + (rbase + r) * 64 + q * 16;
#pragma unroll
        for (int c = 0; c < 4; c++) {
            float2 a = unpack2(acc[c * 2]), bq = unpack2(acc[c * 2 + 1]);
            *reinterpret_cast<float4*>(go + c * 4) = make_float4(a.x, a.y, bq.x, bq.y);
        }
        __threadfence();
        __syncthreads();
        if (tid == 0) atomicAdd(&g_sync[16 + (fblk >> 6)], 1);
    } else if (blockIdx.x == PREP_ID) {
        // ==================== weight split prep (producer) ================
        for (int i = tid; i < 64 * 64; i += 256) {     // W2: n=i>>6, k=i&63
            int nn = i >> 6, k = i & 63;
            float v = W2[k * 64 + nn];
            u32 bits = __float_as_uint(v);
            float lo = v - __uint_as_float(bits & 0xFFFF0000u);
            int w = nn * 32 + (k >> 1);
            ((u16*)g_W2h)[w * 2 + (k & 1)] = (u16)(bits >> 16);
            ((u16*)g_W2l)[w * 2 + (k & 1)] = __bfloat16_as_ushort(__float2bfloat16(lo));
        }
        for (int i = tid; i < 128 * 64; i += 256) {    // W3
            int nn = i >> 6, k = i & 63;
            float v = W3[k * 128 + nn];
            u32 bits = __float_as_uint(v);
            float lo = v - __uint_as_float(bits & 0xFFFF0000u);
            int w = nn * 32 + (k >> 1);
            ((u16*)g_W3h)[w * 2 + (k & 1)] = (u16)(bits >> 16);
            ((u16*)g_W3l)[w * 2 + (k & 1)] = __bfloat16_as_ushort(__float2bfloat16(lo));
        }
        __threadfence();
        __syncthreads();
        if (tid == 0) atomicAdd(&g_sync[32], 1);
    } else {
        // ========================= center (consumer) ======================
        CKS& s = sm.u.center;
        int wid = tid >> 5, lane = tid & 31;
        int cblk = blockIdx.x - CENTER0;
        int b  = cblk & 15;            // m-major interleave across batches
        int m2 = cblk >> 4;
        int c0 = b * MCTR + m2 * 2;
        const float* pb = pos + (size_t)b * NPTS * 3;

        if (tid == 0) {
            while (ld_acq(&g_sync[32]) < 1)        __nanosleep(128);
            while (ld_acq(&g_sync[16 + b]) < 64)   __nanosleep(128);
            int need = (m2 * 2 & 1023) + 2;
            while (ld_acq(&g_sync[b]) < need)      __nanosleep(128);
            __threadfence();
        }
        __syncthreads();

        if (tid == 0) {
            s.cnt[0] = 0; s.cnt[1] = 0;
            int ci0 = g_idx[c0], ci1 = g_idx[c0 + 1];
            s.ctr[0] = pb[ci0 * 3 + 0]; s.ctr[1] = pb[ci0 * 3 + 1]; s.ctr[2] = pb[ci0 * 3 + 2];
            s.ctr[3] = pb[ci1 * 3 + 0]; s.ctr[4] = pb[ci1 * 3 + 1]; s.ctr[5] = pb[ci1 * 3 + 2];
        }
        if (tid < 128) {
            s.nbr[tid] = 0;
            s.rel[tid * 3 + 0] = 0.f; s.rel[tid * 3 + 1] = 0.f; s.rel[tid * 3 + 2] = 0.f;
        }

        // ---- weight copy (pre-split u32s, L2-resident) ----
        for (int i = tid; i < 64 * 32; i += 256) {
            int nn = i >> 5, kk = i & 31;
            s.W2h[nn * AST + kk] = g_W2h[i];
            s.W2l[nn * AST + kk] = g_W2l[i];
        }
        for (int i = tid; i < 128 * 32; i += 256) {
            int nn = i >> 5, kk = i & 31;
            s.W3h[nn * AST + kk] = g_W3h[i];
            s.W3l[nn * AST + kk] = g_W3l[i];
        }
        if (tid < 192) s.w1b[tid] = W1[64 * 64 + tid];
        if (tid < 64)       { s.b1s[tid] = b1[tid]; s.b2s[tid] = b2[tid]; }
        else if (tid < 192) s.b3s[tid - 64] = b3[tid - 64];
        __syncthreads();
        float cx0 = s.ctr[0], cy0 = s.ctr[1], cz0 = s.ctr[2];
        float cx1 = s.ctr[3], cy1 = s.ctr[4], cz1 = s.ctr[5];

        // ---- phase 1: shared candidate scan ----
        for (int i = tid; i < NPTS; i += 256) {
            float X = pb[i * 3 + 0], Y = pb[i * 3 + 1], Z = pb[i * 3 + 2];
            float dx0 = X - cx0, dy0 = Y - cy0, dz0 = Z - cz0;
            float d20 = fmaf(dx0, dx0, fmaf(dy0, dy0, dz0 * dz0));
            if (d20 <= R2C) {
                int p = atomicAdd(&s.cnt[0], 1);
                if (p < CANDC) s.keys[p] = ((ull)__float_as_uint(d20) << 32) | (unsigned)i;
            }
            float dx1 = X - cx1, dy1 = Y - cy1, dz1 = Z - cz1;
            float d21 = fmaf(dx1, dx1, fmaf(dy1, dy1, dz1 * dz1));
            if (d21 <= R2C) {
                int p = atomicAdd(&s.cnt[1], 1);
                if (p < CANDC) s.keys[CANDC + p] = ((ull)__float_as_uint(d21) << 32) | (unsigned)i;
            }
        }
        __syncthreads();

        // ---- phase 2: rank-count selection ----
        for (int cc = 0; cc < 2; cc++) {
            int n  = min(s.cnt[cc], CANDC);
            int nv = min(n, KNBR);
            const ull* kk = s.keys + cc * CANDC;
            float ccx = cc ? cx1 : cx0, ccy = cc ? cy1 : cy0, ccz = cc ? cz1 : cz0;
            ull myk[2]; int rnk[2];
#pragma unroll
            for (int t = 0; t < 2; t++) {
                int i = tid + t * 256;
                myk[t] = (i < n) ? kk[i] : ~0ull;
                rnk[t] = 0;
            }
            for (int j = 0; j < n; j++) {
                ull kj = kk[j];
#pragma unroll
                for (int t = 0; t < 2; t++) rnk[t] += (kj < myk[t]) ? 1 : 0;
            }
#pragma unroll
            for (int t = 0; t < 2; t++) {
                int i = tid + t * 256;
                if (i < n && rnk[t] < KNBR) {
                    int idx = (int)(myk[t] & 0xffffffffu);
                    int slot = cc * 64 + rnk[t];
                    s.nbr[slot] = idx;
                    s.rel[slot * 3 + 0] = pb[idx * 3 + 0] - ccx;
                    s.rel[slot * 3 + 1] = pb[idx * 3 + 1] - ccy;
                    s.rel[slot * 3 + 2] = pb[idx * 3 + 2] - ccz;
                }
            }
            if (tid == 0) s.nvv[cc] = nv;
        }
        __syncthreads();

        int nv0 = s.nvv[0], nv1 = s.nvv[1];

        // ---- h1 (scalar fp32) -> truncation-split bf16 A tile ----
        {
            int row = tid >> 1, half = tid & 1;
            int j = s.nbr[row];
            const float4* gr = reinterpret_cast<const float4*>(
                g_feat + ((size_t)(b * NPTS + j)) * 64 + half * 32);
            float rx = s.rel[row * 3 + 0], ry = s.rel[row * 3 + 1], rz = s.rel[row * 3 + 2];
#pragma unroll
            for (int c4 = 0; c4 < 8; c4++) {
                float4 g = gr[c4];
                float v[4] = {g.x, g.y, g.z, g.w};
                float o[4];
#pragma unroll
                for (int c = 0; c < 4; c++) {
                    int ch = half * 32 + c4 * 4 + c;
                    float t = v[c];
                    t = fmaf(rx, s.w1b[ch], t);
                    t = fmaf(ry, s.w1b[64 + ch], t);
                    t = fmaf(rz, s.w1b[128 + ch], t);
                    o[c] = fmaxf(t + s.b1s[ch], 0.f);
                }
                int w = row * AST + half * 16 + c4 * 2;
                s.Ah[w]     = pack_hi_trunc(o[0], o[1]);
                s.Al[w]     = pack_lo_trunc(o[0], o[1]);
                s.Ah[w + 1] = pack_hi_trunc(o[2], o[3]);
                s.Al[w + 1] = pack_lo_trunc(o[2], o[3]);
            }
        }
        __syncthreads();

        int r0 = wid * 16 + (lane >> 2);
        int lp = lane & 3;

        // per-lane ldmatrix base addresses (shared-space, bytes)
        u32 saA = (u32)__cvta_generic_to_shared(s.Ah);
        u32 aoff = ((u32)(wid * 16 + (lane & 15)) * AST + ((lane >> 4) << 2)) * 4;
        u32 adA_h = saA + aoff;
        u32 adA_l = (u32)__cvta_generic_to_shared(s.Al) + aoff;
        u32 boff = ((u32)(lane & 7) * AST + (((lane >> 3) & 1) << 2)) * 4;
        u32 adW2h = (u32)__cvta_generic_to_shared(s.W2h) + boff;
        u32 adW2l = (u32)__cvta_generic_to_shared(s.W2l) + boff;
        u32 adW3h = (u32)__cvta_generic_to_shared(s.W3h) + boff;
        u32 adW3l = (u32)__cvta_generic_to_shared(s.W3l) + boff;

        // ================= layer 2: h2[128,64] = A @ W2^T =================
        {
            float acc[8][4];
#pragma unroll
            for (int nt = 0; nt < 8; nt++)
#pragma unroll
                for (int c = 0; c < 4; c++) acc[nt][c] = 0.f;

#pragma unroll
            for (int kt = 0; kt < 4; kt++) {
                u32 ah0, ah1, ah2, ah3, al0, al1, al2, al3;
                ldsm4(ah0, ah1, ah2, ah3, adA_h + kt * 32);
                ldsm4(al0, al1, al2, al3, adA_l + kt * 32);
#pragma unroll
                for (int nt = 0; nt < 8; nt++) {
                    u32 bh0, bh1, bl0, bl1;
                    ldsm2(bh0, bh1, adW2h + nt * (8 * AST * 4) + kt * 32);
                    ldsm2(bl0, bl1, adW2l + nt * (8 * AST * 4) + kt * 32);
                    mma16816(acc[nt], ah0, ah1, ah2, ah3, bh0, bh1);
                    mma16816(acc[nt], ah0, ah1, ah2, ah3, bl0, bl1);
                    mma16816(acc[nt], al0, al1, al2, al3, bh0, bh1);
                }
            }
#pragma unroll
            for (int nt = 0; nt < 8; nt++) {
                int cn = nt * 8 + lp * 2;
                float bb0 = s.b2s[cn], bb1 = s.b2s[cn + 1];
                float v0 = fmaxf(acc[nt][0] + bb0, 0.f);
                float v1 = fmaxf(acc[nt][1] + bb1, 0.f);
                float v2 = fmaxf(acc[nt][2] + bb0, 0.f);
                float v3 = fmaxf(acc[nt][3] + bb1, 0.f);
                int w = nt * 4 + lp;
                s.Ah[r0 * AST + w]       = pack_hi_trunc(v0, v1);
                s.Al[r0 * AST + w]       = pack_lo_trunc(v0, v1);
                s.Ah[(r0 + 8) * AST + w] = pack_hi_trunc(v2, v3);
                s.Al[(r0 + 8) * AST + w] = pack_lo_trunc(v2, v3);
            }
        }
        __syncwarp();

        // ================= layer 3: out[128,128] = A @ W3^T + masked max ====
        {
            int rin = (wid & 3) * 16 + (lane >> 2);
            int nv  = (wid >> 2) ? nv1 : nv0;
            bool va = rin < nv, vb = (rin + 8) < nv;

            for (int hhalf = 0; hhalf < 2; hhalf++) {
                float acc[8][4];
#pragma unroll
                for (int nt = 0; nt < 8; nt++)
#pragma unroll
                    for (int c = 0; c < 4; c++) acc[nt][c] = 0.f;

#pragma unroll
                for (int kt = 0; kt < 4; kt++) {
                    u32 ah0, ah1, ah2, ah3, al0, al1, al2, al3;
                    ldsm4(ah0, ah1, ah2, ah3, adA_h + kt * 32);
                    ldsm4(al0, al1, al2, al3, adA_l + kt * 32);
#pragma unroll
                    for (int nt = 0; nt < 8; nt++) {
                        u32 off = (u32)(hhalf * 64 + nt * 8) * AST * 4 + kt * 32;
                        u32 bh0, bh1, bl0, bl1;
                        ldsm2(bh0, bh1, adW3h + off);
                        ldsm2(bl0, bl1, adW3l + off);
                        mma16816(acc[nt], ah0, ah1, ah2, ah3, bh0, bh1);
                        mma16816(acc[nt], ah0, ah1, ah2, ah3, bl0, bl1);
                        mma16816(acc[nt], al0, al1, al2, al3, bh0, bh1);
                    }
                }
#pragma unroll
                for (int nt = 0; nt < 8; nt++) {
                    float m0 = fmaxf(va ? acc[nt][0] : -1e30f, vb ? acc[nt][2] : -1e30f);
                    float m1 = fmaxf(va ? acc[nt][1] : -1e30f, vb ? acc[nt][3] : -1e30f);
#pragma unroll
                    for (int off = 16; off >= 4; off >>= 1) {
                        m0 = fmaxf(m0, __shfl_down_sync(0xffffffffu, m0, off));
                        m1 = fmaxf(m1, __shfl_down_sync(0xffffffffu, m1, off));
                    }
                    if (lane < 4) {
                        int cn = hhalf * 64 + nt * 8 + lane * 2;
                        s.pool[wid][cn]     = m0;
                        s.pool[wid][cn + 1] = m1;
                    }
                }
            }
        }
        __syncthreads();

        // ---- combine 4 warps per center + bias ----
        {
            int center = tid >> 7, ch = tid & 127;
            int w0 = center * 4;
            float v = s.pool[w0][ch];
            v = fmaxf(v, s.pool[w0 + 1][ch]);
            v = fmaxf(v, s.pool[w0 + 2][ch]);
            v = fmaxf(v, s.pool[w0 + 3][ch]);
            out[(size_t)(c0 + center) * OUTD + ch] = v + s.b3s[ch];
        }
    }
}

// =========================================================================
extern "C" void kernel_launch(void* const* d_in, const int* in_sizes, int n_in,
                              void* d_out, int out_size)
{
    const float* x   = (const float*)d_in[0];
    const float* pos = (const float*)d_in[1];
    const float* W1  = (const float*)d_in[2];
    const float* b1  = (const float*)d_in[3];
    const float* W2  = (const float*)d_in[4];
    const float* b2  = (const float*)d_in[5];
    const float* W3  = (const float*)d_in[6];
    const float* b3  = (const float*)d_in[7];

    float* out       = (float*)d_out;
    float* pos_s_out = out + (size_t)BATCH * MCTR * OUTD;

    cudaFuncSetAttribute(fused_kernel,
                         cudaFuncAttributeMaxDynamicSharedMemorySize, (int)sizeof(FSmem));

    void* sp = nullptr;
    cudaGetSymbolAddress(&sp, g_sync);
    cudaMemsetAsync(sp, 0, 48 * sizeof(int), 0);

    fused_kernel<<<GRID_ALL, 256, sizeof(FSmem)>>>(
        pos, pos_s_out, x, W1, W2, W3, b1, b2, b3, out);
}